// round 7
// baseline (speedup 1.0000x reference)
#include <cuda_runtime.h>
#include <cuda_bf16.h>
#include <mma.h>
#include <cstdint>

using namespace nvcuda;

#define BSZ 8
#define HID 64
#define NV  1024
#define NT  64
#define NTHR 512

// bf16 hi/lo split state [buf][(b*64+hid)*NV + v]
__device__ __nv_bfloat16 g_hh[2][BSZ * HID * NV];
__device__ __nv_bfloat16 g_hl[2][BSZ * HID * NV];
__device__ __nv_bfloat16 g_gh[NV * NV];       // graph hi  [w][v]
__device__ __nv_bfloat16 g_gl[NV * NV];       // graph lo
__device__ __nv_bfloat16 g_whh_h[192 * 64];   // W_hh hi [gate][hid]
__device__ __nv_bfloat16 g_whh_l[192 * 64];
__device__ float g_xh[BSZ][NV];
__device__ int   g_mask_mode;                 // 0=byte, 1=int32, 2=float32

// smem byte offsets (buffers aliased after GEMM)
#define OFF_AH(b) ((b) * 9216)
#define OFF_AL(b) (18432 + (b) * 9216)
#define OFF_BH(b) (36864 + (b) * 9216)
#define OFF_BL(b) (55296 + (b) * 9216)
#define OFF_HD   0          // f32 [64][72]  (aliases AH)
#define OFF_HDH  18432      // bf16 [64][72] (aliases AL)
#define OFF_HDL  27648
#define OFF_GD   73728      // f32 [192][72]
#define OFF_HN   129024     // f32 [64][72]
#define OFF_XG   147456     // f32 [64]
#define OFF_PART 147712     // f32 [1024]
#define OFF_SX   151808     // f32 [64]  x(t+1)
#define OFF_SMK  152064     // f32 [64]  mask(t+1) as 0/1
#define SMEM_TOTAL 152320

// ---------------------------------------------------------------------------
__device__ __forceinline__ void cp_async16(uint32_t s, const void* g) {
    asm volatile("cp.async.ca.shared.global [%0], [%1], 16;" :: "r"(s), "l"(g));
}
__device__ __forceinline__ void cp_commit() { asm volatile("cp.async.commit_group;"); }
__device__ __forceinline__ void cp_wait0()  { asm volatile("cp.async.wait_group 0;"); }
__device__ __forceinline__ void cp_wait1()  { asm volatile("cp.async.wait_group 1;"); }
__device__ __forceinline__ void stcs(float* p, float v) {
    asm volatile("st.global.cs.f32 [%0], %1;" :: "l"(p), "f"(v));
}

// ---------------------------------------------------------------------------
__global__ void detect_mask_kernel(const unsigned int* __restrict__ m) {
    __shared__ int viol_i, viol_f;
    if (threadIdx.x == 0) { viol_i = 0; viol_f = 0; }
    __syncthreads();
    int li = 0, lf = 0;
    const int nwords = (BSZ * NV * NT) / 4;
    for (int i = threadIdx.x; i < nwords; i += blockDim.x) {
        unsigned int w = m[i];
        if (w > 1u) li = 1;
        if (w != 0u && w != 0x3F800000u) lf = 1;
    }
    if (li) atomicOr(&viol_i, 1);
    if (lf) atomicOr(&viol_f, 1);
    __syncthreads();
    if (threadIdx.x == 0)
        g_mask_mode = (!viol_f) ? 2 : ((!viol_i) ? 1 : 0);
}

__global__ void split_graph_kernel(const float* __restrict__ graph) {
    int i = blockIdx.x * blockDim.x + threadIdx.x;
    float v = graph[i];
    __nv_bfloat16 hi = __float2bfloat16(v);
    g_gh[i] = hi;
    g_gl[i] = __float2bfloat16(v - __bfloat162float(hi));
}

__global__ void split_whh_kernel(const float* __restrict__ W_hh) {
    int i = blockIdx.x * blockDim.x + threadIdx.x;
    float v = W_hh[i];
    __nv_bfloat16 hi = __float2bfloat16(v);
    g_whh_h[i] = hi;
    g_whh_l[i] = __float2bfloat16(v - __bfloat162float(hi));
}

__global__ void init_h_kernel(const float* __restrict__ h0) {
    int idx = blockIdx.x * blockDim.x + threadIdx.x;   // (b*64+hh)*NV + v
    int v  = idx & (NV - 1);
    int hh = (idx >> 10) & 63;
    float val = h0[hh * NV + v];
    __nv_bfloat16 hi = __float2bfloat16(val);
    g_hh[0][idx] = hi;
    g_hl[0][idx] = __float2bfloat16(val - __bfloat162float(hi));
}

// t=0 prep from h0 directly. Grid (4, 8), 256 threads.
__global__ void prep_kernel(
    const float* __restrict__ x, const unsigned char* __restrict__ mask_raw,
    const float* __restrict__ h0,
    const float* __restrict__ W_init, const float* __restrict__ b_init,
    float* __restrict__ out_preds)
{
    int b = blockIdx.y;
    int v = blockIdx.x * 256 + threadIdx.x;
    float d = 0.f;
    #pragma unroll 16
    for (int hh = 0; hh < HID; hh++) d += W_init[hh] * h0[hh * NV + v];
    d += b_init[0];
    int xi = (b * NV + v) * NT + 0;
    int mode = g_mask_mode;
    bool m;
    if (mode == 0)      m = mask_raw[xi] != 0;
    else if (mode == 1) m = ((const int*)mask_raw)[xi] != 0;
    else                m = ((const float*)mask_raw)[xi] != 0.f;
    g_xh[b][v] = m ? x[xi] : d;
    out_preds[xi] = d;
}

// ---------------------------------------------------------------------------
// Step kernel: grid (16 w-tiles, 8 batches), 512 threads (16 warps).
// ---------------------------------------------------------------------------
__global__ void __launch_bounds__(NTHR) step_tc_kernel(int t, int cur,
    const float* __restrict__ x, const unsigned char* __restrict__ mask_raw,
    const float* __restrict__ ind_graph,
    const float* __restrict__ W_init, const float* __restrict__ b_init,
    const float* __restrict__ W_out,  const float* __restrict__ b_out,
    const float* __restrict__ W_ih,
    const float* __restrict__ b_ih,   const float* __restrict__ b_hh,
    float* __restrict__ out_imps, float* __restrict__ out_preds,
    float* __restrict__ out_reprs)
{
    extern __shared__ __align__(32) char smem[];
    const uint32_t sbase = (uint32_t)__cvta_generic_to_shared(smem);

    const int tid  = threadIdx.x;
    const int wid  = tid >> 5;
    const int wt   = blockIdx.x;
    const int b    = blockIdx.y;          // batch == m-tile
    const int w0   = wt * 64;
    const int m0   = b * 64;
    const int nxt  = cur ^ 1;

    float* hd   = (float*)(smem + OFF_HD);
    __nv_bfloat16* hdh = (__nv_bfloat16*)(smem + OFF_HDH);
    __nv_bfloat16* hdl = (__nv_bfloat16*)(smem + OFF_HDL);
    float* gd   = (float*)(smem + OFF_GD);
    float* hn   = (float*)(smem + OFF_HN);
    float* xg   = (float*)(smem + OFF_XG);
    float* part = (float*)(smem + OFF_PART);
    float* sx   = (float*)(smem + OFF_SX);
    float* smk  = (float*)(smem + OFF_SMK);

    // fill(kt): cp.async 4 bf16 tiles (Ah, Al, Bh, Bl), 64 rows x 64 cols, ld=72.
    auto fill = [&](int kt) {
        int buf = kt & 1;
        int v0  = kt * 64;
        const __nv_bfloat16* srcs[4] = {
            g_hh[cur] + (size_t)m0 * NV + v0,
            g_hl[cur] + (size_t)m0 * NV + v0,
            g_gh      + (size_t)w0 * NV + v0,
            g_gl      + (size_t)w0 * NV + v0 };
        const uint32_t dsts[4] = {
            sbase + OFF_AH(buf), sbase + OFF_AL(buf),
            sbase + OFF_BH(buf), sbase + OFF_BL(buf) };
        int row = tid >> 3, kc = tid & 7;          // 512 chunks per matrix
        #pragma unroll
        for (int mat = 0; mat < 4; mat++)
            cp_async16(dsts[mat] + row * 144 + kc * 16,
                       srcs[mat] + row * NV + kc * 8);
        cp_commit();
    };

    fill(0);

    // ---- prefetch x/mask for t+1 (fully overlapped with everything) ----
    if (tid >= NTHR - 64 && t < NT - 1) {
        int w = tid - (NTHR - 64);
        int xi = (b * NV + w0 + w) * NT + (t + 1);
        int mode = g_mask_mode;
        bool m;
        if (mode == 0)      m = mask_raw[xi] != 0;
        else if (mode == 1) m = ((const int*)mask_raw)[xi] != 0;
        else                m = ((const float*)mask_raw)[xi] != 0.f;
        smk[w] = m ? 1.f : 0.f;
        sx[w]  = x[xi];
    }

    // ---- x_g[w] = sum_v g_xh[b][v] * ind_graph[w0+w][v] (overlaps tile-0) ----
    {
        int w = tid & 63, q = tid >> 6;            // q = 0..7, 128 v each
        const float4* ig = (const float4*)&ind_graph[(w0 + w) * NV + q * 128];
        const float4* xh = (const float4*)&g_xh[b][q * 128];
        float s = 0.f;
        #pragma unroll 8
        for (int j = 0; j < 32; j++) {
            float4 a = ig[j], c = xh[j];
            s += a.x * c.x + a.y * c.y + a.z * c.z + a.w * c.w;
        }
        part[q * 64 + w] = s;
    }
    __syncthreads();
    if (tid < 64) {
        float s = 0.f;
        #pragma unroll
        for (int q = 0; q < 8; q++) s += part[q * 64 + tid];
        xg[tid] = s;
    }

    // ---- GEMM: 16 warps, each owns one 16x16 tile (wm = wid&3, wn = wid>>2) ----
    wmma::fragment<wmma::accumulator, 16, 16, 16, float> acc;
    wmma::fill_fragment(acc, 0.f);
    const int wm = wid & 3, wn = wid >> 2;

    for (int kt = 0; kt < 16; kt++) {
        if (kt < 15) { fill(kt + 1); cp_wait1(); } else { cp_wait0(); }
        __syncthreads();                         // buffer kt ready
        const int buf = kt & 1;
        const __nv_bfloat16* Ah = (const __nv_bfloat16*)(smem + OFF_AH(buf));
        const __nv_bfloat16* Al = (const __nv_bfloat16*)(smem + OFF_AL(buf));
        const __nv_bfloat16* Bh = (const __nv_bfloat16*)(smem + OFF_BH(buf));
        const __nv_bfloat16* Bl = (const __nv_bfloat16*)(smem + OFF_BL(buf));
        #pragma unroll
        for (int ks = 0; ks < 4; ks++) {
            wmma::fragment<wmma::matrix_a, 16, 16, 16, __nv_bfloat16, wmma::row_major> fah, fal;
            wmma::fragment<wmma::matrix_b, 16, 16, 16, __nv_bfloat16, wmma::col_major> fbh, fbl;
            wmma::load_matrix_sync(fah, Ah + wm * 16 * 72 + ks * 16, 72);
            wmma::load_matrix_sync(fal, Al + wm * 16 * 72 + ks * 16, 72);
            wmma::load_matrix_sync(fbh, Bh + wn * 16 * 72 + ks * 16, 72);
            wmma::load_matrix_sync(fbl, Bl + wn * 16 * 72 + ks * 16, 72);
            wmma::mma_sync(acc, fah, fbh, acc);
            wmma::mma_sync(acc, fah, fbl, acc);
            wmma::mma_sync(acc, fal, fbh, acc);
        }
        __syncthreads();                         // all reads done before refill
    }

    // ---- store h_diff (f32) into smem [64][72] (aliases dead buffers) ----
    wmma::store_matrix_sync(hd + wm * 16 * 72 + wn * 16, acc, 72, wmma::mem_row_major);
    __syncthreads();

    // ---- split h_diff -> bf16 hi/lo for the gate GEMM ----
    #pragma unroll
    for (int i = 0; i < 8; i++) {
        int idx = tid + i * NTHR;              // 4096
        int row = idx >> 6, col = idx & 63;
        float v = hd[row * 72 + col];
        __nv_bfloat16 hi = __float2bfloat16(v);
        hdh[row * 72 + col] = hi;
        hdl[row * 72 + col] = __float2bfloat16(v - __bfloat162float(hi));
    }
    __syncthreads();

    // ---- gates GEMM: gd[192 x 64] = W_hh · h_diff; 48 tiles, 3 per warp ----
    {
        #pragma unroll
        for (int i = 0; i < 3; i++) {
            int tile = wid * 3 + i;
            int gm = tile >> 2, gn = tile & 3;
            wmma::fragment<wmma::accumulator, 16, 16, 16, float> gacc;
            wmma::fill_fragment(gacc, 0.f);
            #pragma unroll
            for (int ks = 0; ks < 4; ks++) {
                wmma::fragment<wmma::matrix_a, 16, 16, 16, __nv_bfloat16, wmma::row_major> fah, fal;
                wmma::fragment<wmma::matrix_b, 16, 16, 16, __nv_bfloat16, wmma::row_major> gbh, gbl;
                int aoff = gm * 16 * 64 + ks * 16;
                int boff = ks * 16 * 72 + gn * 16;
                wmma::load_matrix_sync(fah, g_whh_h + aoff, 64);
                wmma::load_matrix_sync(fal, g_whh_l + aoff, 64);
                wmma::load_matrix_sync(gbh, hdh + boff, 72);
                wmma::load_matrix_sync(gbl, hdl + boff, 72);
                wmma::mma_sync(gacc, fah, gbh, gacc);
                wmma::mma_sync(gacc, fah, gbl, gacc);
                wmma::mma_sync(gacc, fal, gbh, gacc);
            }
            wmma::store_matrix_sync(gd + gm * 16 * 72 + gn * 16, gacc, 72,
                                    wmma::mem_row_major);
        }
    }
    __syncthreads();

    // ---- nonlinearity + state update: thread = (hh, wq), 8 nodes ----
    {
        const int hh = tid >> 3;
        const int wq = tid & 7;
        float wih_r = W_ih[hh],  wih_z = W_ih[64 + hh],  wih_n = W_ih[128 + hh];
        float bi_r  = b_ih[hh] + b_hh[hh];
        float bi_z  = b_ih[64 + hh] + b_hh[64 + hh];
        float bi_n  = b_ih[128 + hh];
        float bh_n  = b_hh[128 + hh];
        #pragma unroll
        for (int k = 0; k < 8; k++) {
            int w = wq + 8 * k;
            float ar = gd[hh * 72 + w];
            float az = gd[(64 + hh) * 72 + w];
            float an = gd[(128 + hh) * 72 + w];
            float xgv = xg[w];
            float r = 1.f / (1.f + __expf(-(ar + wih_r * xgv + bi_r)));
            float z = 1.f / (1.f + __expf(-(az + wih_z * xgv + bi_z)));
            float n = tanhf(wih_n * xgv + bi_n + r * (an + bh_n));
            float hd_self = hd[hh * 72 + w];
            float hnew = (1.f - z) * n + z * hd_self;
            size_t si = (size_t)(m0 + hh) * NV + w0 + w;
            __nv_bfloat16 hi = __float2bfloat16(hnew);
            g_hh[nxt][si] = hi;
            g_hl[nxt][si] = __float2bfloat16(hnew - __bfloat162float(hi));
            stcs(&out_reprs[((b * HID + hh) * NV + (w0 + w)) * NT + t], hnew);
            hn[hh * 72 + w] = hnew;
        }
    }
    __syncthreads();

    // ---- fused epilogue: imps(t), preds(t+1), g_xh(t+1) ----
    {
        int w = tid & 63, q = tid >> 6;           // q: 8 hid values each
        float so = 0.f, si = 0.f;
        #pragma unroll
        for (int j = 0; j < 8; j++) {
            int hh = q * 8 + j;
            float hv = hn[hh * 72 + w];
            so += W_out[hh]  * hv;
            si += W_init[hh] * hv;
        }
        part[q * 64 + w]       = so;
        part[512 + q * 64 + w] = si;
    }
    __syncthreads();
    if (tid < 64) {
        int w = tid;
        float so = 0.f, si = 0.f;
        #pragma unroll
        for (int q = 0; q < 8; q++) {
            so += part[q * 64 + w];
            si += part[512 + q * 64 + w];
        }
        stcs(&out_imps[(b * NV + w0 + w) * NT + t], so + b_out[0]);
        if (t < NT - 1) {
            float d = si + b_init[0];
            int xi = (b * NV + w0 + w) * NT + (t + 1);
            g_xh[b][w0 + w] = (smk[w] != 0.f) ? sx[w] : d;
            stcs(&out_preds[xi], d);
        }
    }
}

// ---------------------------------------------------------------------------
extern "C" void kernel_launch(void* const* d_in, const int* in_sizes, int n_in,
                              void* d_out, int out_size) {
    const float* x          = (const float*)d_in[0];
    const unsigned char* mk = (const unsigned char*)d_in[1];
    const float* graph      = (const float*)d_in[2];
    const float* ind_graph  = (const float*)d_in[3];
    const float* h0         = (const float*)d_in[4];
    const float* W_init     = (const float*)d_in[5];
    const float* b_init     = (const float*)d_in[6];
    const float* W_out      = (const float*)d_in[7];
    const float* b_out      = (const float*)d_in[8];
    const float* W_ih       = (const float*)d_in[9];
    const float* W_hh       = (const float*)d_in[10];
    const float* b_ih       = (const float*)d_in[11];
    const float* b_hh       = (const float*)d_in[12];

    float* out_imps  = (float*)d_out;
    float* out_preds = out_imps + BSZ * NV * NT;
    float* out_reprs = out_preds + BSZ * NV * NT;

    cudaFuncSetAttribute(step_tc_kernel, cudaFuncAttributeMaxDynamicSharedMemorySize,
                         SMEM_TOTAL);

    detect_mask_kernel<<<1, 256>>>((const unsigned int*)mk);
    split_graph_kernel<<<NV * NV / 256, 256>>>(graph);
    split_whh_kernel<<<192 * 64 / 256, 256>>>(W_hh);
    init_h_kernel<<<BSZ * HID * NV / 256, 256>>>(h0);
    prep_kernel<<<dim3(4, BSZ), 256>>>(x, mk, h0, W_init, b_init, out_preds);
    for (int t = 0; t < NT; t++) {
        step_tc_kernel<<<dim3(16, BSZ), NTHR, SMEM_TOTAL>>>(
            t, t & 1, x, mk, ind_graph,
            W_init, b_init, W_out, b_out, W_ih, b_ih, b_hh,
            out_imps, out_preds, out_reprs);
    }
}

// round 8
// speedup vs baseline: 1.1250x; 1.1250x over previous
#include <cuda_runtime.h>
#include <cuda_bf16.h>
#include <mma.h>
#include <cstdint>

using namespace nvcuda;

#define BSZ 8
#define HID 64
#define NV  1024
#define NT  64

// bf16 hi/lo split state [buf][(b*64+hid)*NV + v]
__device__ __nv_bfloat16 g_hh[2][BSZ * HID * NV];
__device__ __nv_bfloat16 g_hl[2][BSZ * HID * NV];
__device__ __nv_bfloat16 g_gh[NV * NV];       // graph hi  [w][v]
__device__ __nv_bfloat16 g_gl[NV * NV];       // graph lo
__device__ __nv_bfloat16 g_whh_h[192 * 64];   // W_hh hi [gate][hid]
__device__ __nv_bfloat16 g_whh_l[192 * 64];
__device__ float g_xh[BSZ][NV];
__device__ int   g_mask_mode;                 // 0=byte, 1=int32, 2=float32

// smem byte offsets (buffers aliased after GEMM)
#define OFF_AH(b) ((b) * 9216)
#define OFF_AL(b) (18432 + (b) * 9216)
#define OFF_BH(b) (36864 + (b) * 9216)
#define OFF_BL(b) (55296 + (b) * 9216)
#define OFF_HD   0          // f32 [64][72]  (aliases AH)
#define OFF_HDH  18432      // bf16 [64][72] (aliases AL)
#define OFF_HDL  27648
#define OFF_GD   73728      // f32 [192][72]
#define OFF_HN   129024     // f32 [64][72]
#define OFF_XG   147456     // f32 [64]
#define OFF_PART 147712     // f32 [512]
#define OFF_SX   149760     // f32 [64]  x(t+1)
#define OFF_SMK  150016     // f32 [64]  mask(t+1) as 0/1
#define OFF_WH   150272     // bf16 [192][64] W_hh hi
#define OFF_WL   174848     // bf16 [192][64] W_hh lo
#define SMEM_TOTAL 199424

// ---------------------------------------------------------------------------
__device__ __forceinline__ void cp_async16(uint32_t s, const void* g) {
    asm volatile("cp.async.ca.shared.global [%0], [%1], 16;" :: "r"(s), "l"(g));
}
__device__ __forceinline__ void cp_commit() { asm volatile("cp.async.commit_group;"); }
__device__ __forceinline__ void cp_wait0()  { asm volatile("cp.async.wait_group 0;"); }
__device__ __forceinline__ void cp_wait1()  { asm volatile("cp.async.wait_group 1;"); }
__device__ __forceinline__ void stcs(float* p, float v) {
    asm volatile("st.global.cs.f32 [%0], %1;" :: "l"(p), "f"(v));
}
__device__ __forceinline__ float tanh_fast(float x) {
    float y;
    asm("tanh.approx.f32 %0, %1;" : "=f"(y) : "f"(x));
    return y;
}

// ---------------------------------------------------------------------------
__global__ void detect_mask_kernel(const unsigned int* __restrict__ m) {
    __shared__ int viol_i, viol_f;
    if (threadIdx.x == 0) { viol_i = 0; viol_f = 0; }
    __syncthreads();
    int li = 0, lf = 0;
    const int nwords = (BSZ * NV * NT) / 4;
    for (int i = threadIdx.x; i < nwords; i += blockDim.x) {
        unsigned int w = m[i];
        if (w > 1u) li = 1;
        if (w != 0u && w != 0x3F800000u) lf = 1;
    }
    if (li) atomicOr(&viol_i, 1);
    if (lf) atomicOr(&viol_f, 1);
    __syncthreads();
    if (threadIdx.x == 0)
        g_mask_mode = (!viol_f) ? 2 : ((!viol_i) ? 1 : 0);
}

// Merged one-time setup: graph split (1M), W_hh split (12K), h0 init (512K).
__global__ void setup_kernel(const float* __restrict__ graph,
                             const float* __restrict__ W_hh,
                             const float* __restrict__ h0) {
    int i = blockIdx.x * blockDim.x + threadIdx.x;     // 0 .. NV*NV-1
    {
        float v = graph[i];
        __nv_bfloat16 hi = __float2bfloat16(v);
        g_gh[i] = hi;
        g_gl[i] = __float2bfloat16(v - __bfloat162float(hi));
    }
    if (i < 192 * 64) {
        float v = W_hh[i];
        __nv_bfloat16 hi = __float2bfloat16(v);
        g_whh_h[i] = hi;
        g_whh_l[i] = __float2bfloat16(v - __bfloat162float(hi));
    }
    if (i < BSZ * HID * NV) {
        int v  = i & (NV - 1);
        int hh = (i >> 10) & 63;
        float val = h0[hh * NV + v];
        __nv_bfloat16 hi = __float2bfloat16(val);
        g_hh[0][i] = hi;
        g_hl[0][i] = __float2bfloat16(val - __bfloat162float(hi));
    }
}

// t=0 prep from h0 directly. Grid (4, 8), 256 threads.
__global__ void prep_kernel(
    const float* __restrict__ x, const unsigned char* __restrict__ mask_raw,
    const float* __restrict__ h0,
    const float* __restrict__ W_init, const float* __restrict__ b_init,
    float* __restrict__ out_preds)
{
    int b = blockIdx.y;
    int v = blockIdx.x * 256 + threadIdx.x;
    float d = 0.f;
    #pragma unroll 16
    for (int hh = 0; hh < HID; hh++) d += W_init[hh] * h0[hh * NV + v];
    d += b_init[0];
    int xi = (b * NV + v) * NT + 0;
    int mode = g_mask_mode;
    bool m;
    if (mode == 0)      m = mask_raw[xi] != 0;
    else if (mode == 1) m = ((const int*)mask_raw)[xi] != 0;
    else                m = ((const float*)mask_raw)[xi] != 0.f;
    g_xh[b][v] = m ? x[xi] : d;
    out_preds[xi] = d;
}

// ---------------------------------------------------------------------------
// Step kernel: grid (16 w-tiles, 8 batches), 256 threads (8 warps).
// ---------------------------------------------------------------------------
__global__ void __launch_bounds__(256) step_tc_kernel(int t, int cur,
    const float* __restrict__ x, const unsigned char* __restrict__ mask_raw,
    const float* __restrict__ ind_graph,
    const float* __restrict__ W_init, const float* __restrict__ b_init,
    const float* __restrict__ W_out,  const float* __restrict__ b_out,
    const float* __restrict__ W_ih,
    const float* __restrict__ b_ih,   const float* __restrict__ b_hh,
    float* __restrict__ out_imps, float* __restrict__ out_preds,
    float* __restrict__ out_reprs)
{
    extern __shared__ __align__(32) char smem[];
    const uint32_t sbase = (uint32_t)__cvta_generic_to_shared(smem);

    const int tid  = threadIdx.x;
    const int wid  = tid >> 5;
    const int wt   = blockIdx.x;
    const int b    = blockIdx.y;          // batch == m-tile
    const int w0   = wt * 64;
    const int m0   = b * 64;
    const int nxt  = cur ^ 1;

    float* hd   = (float*)(smem + OFF_HD);
    __nv_bfloat16* hdh = (__nv_bfloat16*)(smem + OFF_HDH);
    __nv_bfloat16* hdl = (__nv_bfloat16*)(smem + OFF_HDL);
    float* gd   = (float*)(smem + OFF_GD);
    float* hn   = (float*)(smem + OFF_HN);
    float* xg   = (float*)(smem + OFF_XG);
    float* part = (float*)(smem + OFF_PART);
    float* sx   = (float*)(smem + OFF_SX);
    float* smk  = (float*)(smem + OFF_SMK);
    __nv_bfloat16* swh = (__nv_bfloat16*)(smem + OFF_WH);
    __nv_bfloat16* swl = (__nv_bfloat16*)(smem + OFF_WL);

    // fill(kt): cp.async 4 bf16 tiles (Ah, Al, Bh, Bl), 64 rows x 64 cols, ld=72.
    auto fill = [&](int kt) {
        int buf = kt & 1;
        int v0  = kt * 64;
        const __nv_bfloat16* srcs[4] = {
            g_hh[cur] + (size_t)m0 * NV + v0,
            g_hl[cur] + (size_t)m0 * NV + v0,
            g_gh      + (size_t)w0 * NV + v0,
            g_gl      + (size_t)w0 * NV + v0 };
        const uint32_t dsts[4] = {
            sbase + OFF_AH(buf), sbase + OFF_AL(buf),
            sbase + OFF_BH(buf), sbase + OFF_BL(buf) };
        #pragma unroll
        for (int i = 0; i < 8; i++) {
            const int mat = i >> 1;
            int cc = (i & 1) * 256 + tid;       // 0..511
            int row = cc >> 3, kc = cc & 7;
            cp_async16(dsts[mat] + row * 144 + kc * 16,
                       srcs[mat] + row * NV + kc * 8);
        }
    };

    // prologue group: tile 0 + W_hh hi/lo (one-time, same commit group)
    fill(0);
    {
        #pragma unroll
        for (int r = 0; r < 6; r++) {
            int c = r * 256 + tid;              // 1536 chunks x 16B = 24576 B
            cp_async16(sbase + OFF_WH + c * 16, (const char*)g_whh_h + c * 16);
            cp_async16(sbase + OFF_WL + c * 16, (const char*)g_whh_l + c * 16);
        }
    }
    cp_commit();

    // ---- prefetch x/mask for t+1 (overlapped) ----
    if (tid >= 192 && t < NT - 1) {
        int w = tid - 192;
        int xi = (b * NV + w0 + w) * NT + (t + 1);
        int mode = g_mask_mode;
        bool m;
        if (mode == 0)      m = mask_raw[xi] != 0;
        else if (mode == 1) m = ((const int*)mask_raw)[xi] != 0;
        else                m = ((const float*)mask_raw)[xi] != 0.f;
        smk[w] = m ? 1.f : 0.f;
        sx[w]  = x[xi];
    }

    // ---- x_g[w] = sum_v g_xh[b][v] * ind_graph[w0+w][v] (overlaps tile-0) ----
    {
        int w = tid & 63, q = tid >> 6;
        const float4* ig = (const float4*)&ind_graph[(w0 + w) * NV + q * 256];
        const float4* xh = (const float4*)&g_xh[b][q * 256];
        float s = 0.f;
        #pragma unroll 16
        for (int j = 0; j < 64; j++) {
            float4 a = ig[j], c = xh[j];
            s += a.x * c.x + a.y * c.y + a.z * c.z + a.w * c.w;
        }
        part[q * 64 + w] = s;
    }
    __syncthreads();
    if (tid < 64)
        xg[tid] = part[tid] + part[64 + tid] + part[128 + tid] + part[192 + tid];

    // ---- GEMM: warp (wm = wid&3 -> m-tile, wn = wid>>2 -> 2 n-tiles) ----
    wmma::fragment<wmma::accumulator, 16, 16, 16, float> acc[2];
    wmma::fill_fragment(acc[0], 0.f);
    wmma::fill_fragment(acc[1], 0.f);
    const int wm = wid & 3, wn = wid >> 2;

    for (int kt = 0; kt < 16; kt++) {
        if (kt < 15) { fill(kt + 1); cp_commit(); cp_wait1(); } else { cp_wait0(); }
        __syncthreads();                         // buffer kt ready
        const int buf = kt & 1;
        const __nv_bfloat16* Ah = (const __nv_bfloat16*)(smem + OFF_AH(buf));
        const __nv_bfloat16* Al = (const __nv_bfloat16*)(smem + OFF_AL(buf));
        const __nv_bfloat16* Bh = (const __nv_bfloat16*)(smem + OFF_BH(buf));
        const __nv_bfloat16* Bl = (const __nv_bfloat16*)(smem + OFF_BL(buf));
        #pragma unroll
        for (int ks = 0; ks < 4; ks++) {
            wmma::fragment<wmma::matrix_a, 16, 16, 16, __nv_bfloat16, wmma::row_major> fah, fal;
            wmma::load_matrix_sync(fah, Ah + wm * 16 * 72 + ks * 16, 72);
            wmma::load_matrix_sync(fal, Al + wm * 16 * 72 + ks * 16, 72);
            #pragma unroll
            for (int ni = 0; ni < 2; ni++) {
                wmma::fragment<wmma::matrix_b, 16, 16, 16, __nv_bfloat16, wmma::col_major> fbh, fbl;
                int boff = (wn * 2 + ni) * 16 * 72 + ks * 16;
                wmma::load_matrix_sync(fbh, Bh + boff, 72);
                wmma::load_matrix_sync(fbl, Bl + boff, 72);
                wmma::mma_sync(acc[ni], fah, fbh, acc[ni]);
                wmma::mma_sync(acc[ni], fah, fbl, acc[ni]);
                wmma::mma_sync(acc[ni], fal, fbh, acc[ni]);
            }
        }
        __syncthreads();                         // all reads done before refill
    }

    // ---- store h_diff (f32) into smem [64][72] (aliases dead buffers) ----
    wmma::store_matrix_sync(hd + wm * 16 * 72 + (wn * 2 + 0) * 16, acc[0], 72, wmma::mem_row_major);
    wmma::store_matrix_sync(hd + wm * 16 * 72 + (wn * 2 + 1) * 16, acc[1], 72, wmma::mem_row_major);
    __syncthreads();

    // ---- split h_diff -> bf16 hi/lo for the gate GEMM ----
    #pragma unroll
    for (int i = 0; i < 16; i++) {
        int idx = tid + i * 256;               // 4096
        int row = idx >> 6, col = idx & 63;
        float v = hd[row * 72 + col];
        __nv_bfloat16 hi = __float2bfloat16(v);
        hdh[row * 72 + col] = hi;
        hdl[row * 72 + col] = __float2bfloat16(v - __bfloat162float(hi));
    }
    __syncthreads();

    // ---- gates GEMM: gd[192 x 64] = W_hh · h_diff (W from smem) ----
    {
        const int gm = wid >> 1, gn = wid & 1;   // 3 m-tiles, 2 n-tiles per warp
        wmma::fragment<wmma::accumulator, 16, 16, 16, float> gacc[3][2];
        #pragma unroll
        for (int mi = 0; mi < 3; mi++)
            #pragma unroll
            for (int ni = 0; ni < 2; ni++) wmma::fill_fragment(gacc[mi][ni], 0.f);
        #pragma unroll
        for (int ks = 0; ks < 4; ks++) {
            wmma::fragment<wmma::matrix_b, 16, 16, 16, __nv_bfloat16, wmma::row_major> gbh[2], gbl[2];
            #pragma unroll
            for (int ni = 0; ni < 2; ni++) {
                int boff = ks * 16 * 72 + (gn * 2 + ni) * 16;
                wmma::load_matrix_sync(gbh[ni], hdh + boff, 72);
                wmma::load_matrix_sync(gbl[ni], hdl + boff, 72);
            }
            #pragma unroll
            for (int mi = 0; mi < 3; mi++) {
                wmma::fragment<wmma::matrix_a, 16, 16, 16, __nv_bfloat16, wmma::row_major> fah, fal;
                int aoff = (gm * 3 + mi) * 16 * 64 + ks * 16;
                wmma::load_matrix_sync(fah, swh + aoff, 64);
                wmma::load_matrix_sync(fal, swl + aoff, 64);
                #pragma unroll
                for (int ni = 0; ni < 2; ni++) {
                    wmma::mma_sync(gacc[mi][ni], fah, gbh[ni], gacc[mi][ni]);
                    wmma::mma_sync(gacc[mi][ni], fah, gbl[ni], gacc[mi][ni]);
                    wmma::mma_sync(gacc[mi][ni], fal, gbh[ni], gacc[mi][ni]);
                }
            }
        }
        #pragma unroll
        for (int mi = 0; mi < 3; mi++)
            #pragma unroll
            for (int ni = 0; ni < 2; ni++)
                wmma::store_matrix_sync(gd + (gm * 3 + mi) * 16 * 72 + (gn * 2 + ni) * 16,
                                        gacc[mi][ni], 72, wmma::mem_row_major);
    }
    __syncthreads();

    // ---- nonlinearity + state update (tanh.approx): thread = (hh, wq) ----
    {
        const int hh = tid >> 2;
        const int wq = tid & 3;
        float wih_r = W_ih[hh],  wih_z = W_ih[64 + hh],  wih_n = W_ih[128 + hh];
        float bi_r  = b_ih[hh] + b_hh[hh];
        float bi_z  = b_ih[64 + hh] + b_hh[64 + hh];
        float bi_n  = b_ih[128 + hh];
        float bh_n  = b_hh[128 + hh];
        #pragma unroll
        for (int k = 0; k < 16; k++) {
            int w = wq + 4 * k;
            float ar = gd[hh * 72 + w];
            float az = gd[(64 + hh) * 72 + w];
            float an = gd[(128 + hh) * 72 + w];
            float xgv = xg[w];
            float r = 0.5f + 0.5f * tanh_fast(0.5f * (ar + wih_r * xgv + bi_r));
            float z = 0.5f + 0.5f * tanh_fast(0.5f * (az + wih_z * xgv + bi_z));
            float n = tanh_fast(wih_n * xgv + bi_n + r * (an + bh_n));
            float hd_self = hd[hh * 72 + w];
            float hnew = (1.f - z) * n + z * hd_self;
            size_t si = (size_t)(m0 + hh) * NV + w0 + w;
            __nv_bfloat16 hi = __float2bfloat16(hnew);
            g_hh[nxt][si] = hi;
            g_hl[nxt][si] = __float2bfloat16(hnew - __bfloat162float(hi));
            stcs(&out_reprs[((b * HID + hh) * NV + (w0 + w)) * NT + t], hnew);
            hn[hh * 72 + w] = hnew;
        }
    }
    __syncthreads();

    // ---- fused epilogue: imps(t), preds(t+1), g_xh(t+1) ----
    {
        int w = tid & 63, q = tid >> 6;
        float so = 0.f, si = 0.f;
        #pragma unroll
        for (int j = 0; j < 16; j++) {
            int hh = q * 16 + j;
            float hv = hn[hh * 72 + w];
            so += W_out[hh]  * hv;
            si += W_init[hh] * hv;
        }
        part[q * 64 + w]       = so;
        part[256 + q * 64 + w] = si;
    }
    __syncthreads();
    if (tid < 64) {
        int w = tid;
        float so = part[w] + part[64 + w] + part[128 + w] + part[192 + w];
        stcs(&out_imps[(b * NV + w0 + w) * NT + t], so + b_out[0]);
        if (t < NT - 1) {
            float si = part[256 + w] + part[320 + w] + part[384 + w] + part[448 + w];
            float d = si + b_init[0];
            int xi = (b * NV + w0 + w) * NT + (t + 1);
            g_xh[b][w0 + w] = (smk[w] != 0.f) ? sx[w] : d;
            stcs(&out_preds[xi], d);
        }
    }
}

// ---------------------------------------------------------------------------
extern "C" void kernel_launch(void* const* d_in, const int* in_sizes, int n_in,
                              void* d_out, int out_size) {
    const float* x          = (const float*)d_in[0];
    const unsigned char* mk = (const unsigned char*)d_in[1];
    const float* graph      = (const float*)d_in[2];
    const float* ind_graph  = (const float*)d_in[3];
    const float* h0         = (const float*)d_in[4];
    const float* W_init     = (const float*)d_in[5];
    const float* b_init     = (const float*)d_in[6];
    const float* W_out      = (const float*)d_in[7];
    const float* b_out      = (const float*)d_in[8];
    const float* W_ih       = (const float*)d_in[9];
    const float* W_hh       = (const float*)d_in[10];
    const float* b_ih       = (const float*)d_in[11];
    const float* b_hh       = (const float*)d_in[12];

    float* out_imps  = (float*)d_out;
    float* out_preds = out_imps + BSZ * NV * NT;
    float* out_reprs = out_preds + BSZ * NV * NT;

    cudaFuncSetAttribute(step_tc_kernel, cudaFuncAttributeMaxDynamicSharedMemorySize,
                         SMEM_TOTAL);

    detect_mask_kernel<<<1, 256>>>((const unsigned int*)mk);
    setup_kernel<<<NV * NV / 256, 256>>>(graph, W_hh, h0);
    prep_kernel<<<dim3(4, BSZ), 256>>>(x, mk, h0, W_init, b_init, out_preds);
    for (int t = 0; t < NT; t++) {
        step_tc_kernel<<<dim3(16, BSZ), 256, SMEM_TOTAL>>>(
            t, t & 1, x, mk, ind_graph,
            W_init, b_init, W_out, b_out, W_ih, b_ih, b_hh,
            out_imps, out_preds, out_reprs);
    }
}